// round 14
// baseline (speedup 1.0000x reference)
#include <cuda_runtime.h>
#include <cuda_fp16.h>
#include <cstdint>

#define N_NODES 100000
#define N_EDGES 1600000
#define NB_SCAN 196            // ceil(100000/512)

// Persistent scratch (zero-initialized at module load; scatter re-zeros
// g_degi/g_bsum each call so every graph replay sees the same state).
__device__ __half g_xh [N_NODES * 64];   // fp16 mirror of in_feat
__device__ __half g_h1h[N_NODES * 64];   // fp16 layer-1 output
__device__ int    g_degi[N_NODES];
__device__ int    g_rowptr[N_NODES + 1];
__device__ int    g_cursor[N_NODES];
__device__ int    g_esrc[N_EDGES];
__device__ int    g_bsum[NB_SCAN];

// ---------------- helpers ----------------
__device__ __forceinline__ void st_release(int* p, int v) {
    asm volatile("st.release.gpu.b32 [%0], %1;" :: "l"(p), "r"(v) : "memory");
}
__device__ __forceinline__ int ld_acquire(const int* p) {
    int v;
    asm volatile("ld.acquire.gpu.b32 %0, [%1];" : "=r"(v) : "l"(p) : "memory");
    return v;
}
__device__ __forceinline__ uint32_t s2u(const void* p) {
    return (uint32_t)__cvta_generic_to_shared(p);
}
__device__ __forceinline__ uint32_t h2u(__half2 h) {
    uint32_t u;
    memcpy(&u, &h, 4);
    return u;
}

// ---------------- CSR build ----------------
// (0) histogram + fp16 cast of in_feat.
__global__ void csr_hist_cast(const int* __restrict__ dst,
                              const float4* __restrict__ xin) {
    int e = blockIdx.x * blockDim.x + threadIdx.x;
    if (e < N_EDGES) {
        atomicAdd(&g_degi[dst[e]], 1);
        float4 v = __ldg(&xin[e]);
        __half2* xh2 = (__half2*)g_xh;
        xh2[2 * e]     = __floats2half2_rn(v.x, v.y);
        xh2[2 * e + 1] = __floats2half2_rn(v.z, v.w);
    }
}

// (1) single-pass scan with lookback.
__global__ void scan_lookback() {
    __shared__ int sh[512];
    int t = threadIdx.x, bid = blockIdx.x;
    int idx = bid * 512 + t;
    int v = (idx < N_NODES) ? g_degi[idx] : 0;

    sh[t] = v;
    __syncthreads();
    for (int off = 1; off < 512; off <<= 1) {
        int x = (t >= off) ? sh[t - off] : 0;
        __syncthreads();
        sh[t] += x;
        __syncthreads();
    }
    int incl = sh[t];
    int btot = sh[511];
    if (t == 0) st_release(&g_bsum[bid], btot + 1);

    int pre = 0;
    if (t < bid) {
        int x;
        do { x = ld_acquire(&g_bsum[t]); } while (x == 0);
        pre = x - 1;
    }
    __syncthreads();
    sh[t] = pre;
    __syncthreads();
    for (int off = 256; off > 0; off >>= 1) {
        if (t < off) sh[t] += sh[t + off];
        __syncthreads();
    }
    int excl = incl - v + sh[0];
    if (idx < N_NODES) {
        g_rowptr[idx] = excl;
        g_cursor[idx] = excl;
    }
    if (bid == 0 && t == 0) g_rowptr[N_NODES] = N_EDGES;
}

// (2) scatter + reset degi/bsum for next replay.
__global__ void csr_scatter(const int* __restrict__ src,
                            const int* __restrict__ dst) {
    int e = blockIdx.x * blockDim.x + threadIdx.x;
    if (e < N_EDGES) {
        int p = atomicAdd(&g_cursor[dst[e]], 1);
        g_esrc[p] = src[e];
    }
    if (e < N_NODES) g_degi[e] = 0;
    if (e < NB_SCAN) g_bsum[e] = 0;
}

// ---------------- Fused layer: fp16 gather-mean + HMMA dual GEMM ----------------
// out = act( X @ Ws^T + mean_neigh(X) @ Wn^T + b ), X fp16, fp32 accumulate.
// Gather: 4 edges in flight per node; edge pairs pre-summed with HADD2,
// pair-sums accumulated in fp32.
#define PITCH 72

template <bool LAYER1>
__global__ void __launch_bounds__(512)
sage_fused(const float* __restrict__ Wself,
           const float* __restrict__ Wneigh,
           const float* __restrict__ bias,
           float* __restrict__ outp) {
    __shared__ __align__(16) __half sXh[64 * PITCH];
    __shared__ __align__(16) __half sNh[64 * PITCH];
    __shared__ __align__(16) __half sWsh[64 * PITCH];
    __shared__ __align__(16) __half sWnh[64 * PITCH];

    const uint4* H = LAYER1 ? (const uint4*)g_xh : (const uint4*)g_h1h;

    const int tid  = threadIdx.x;
    const int w    = tid >> 5;
    const int lane = tid & 31;
    const int row0 = blockIdx.x * 64;

    // ---- Stage self tile (fp16 rows straight from H) ----
    {
        int r = tid >> 3, c = tid & 7;       // 64 rows x 8 uint4 chunks
        int gr = row0 + r;
        uint4 v = make_uint4(0u, 0u, 0u, 0u);
        if (gr < N_NODES) v = __ldg(&H[gr * 8 + c]);
        *(uint4*)(sXh + r * PITCH + c * 8) = v;
    }

    // ---- Stage weights fp32 -> fp16 ([n][k] layout) ----
    {
        const float4* Ws4 = (const float4*)Wself;
        const float4* Wn4 = (const float4*)Wneigh;
#pragma unroll
        for (int l = 0; l < 2; l++) {
            int i = tid + l * 512;           // 0..1023 float4 index
            int r = i >> 4, f = i & 15;      // row (n), 4-col (k) chunk
            float4 a = __ldg(&Ws4[i]);
            float4 b = __ldg(&Wn4[i]);
            __half2* ps = (__half2*)(sWsh + r * PITCH + f * 4);
            __half2* pn = (__half2*)(sWnh + r * PITCH + f * 4);
            ps[0] = __floats2half2_rn(a.x, a.y);
            ps[1] = __floats2half2_rn(a.z, a.w);
            pn[0] = __floats2half2_rn(b.x, b.y);
            pn[1] = __floats2half2_rn(b.z, b.w);
        }
    }

    // ---- Gather-mean (fp16 rows, 128B = 1 line/edge) -> sNh ----
    // 8 lanes per node -> 4 nodes concurrently per warp; 4 edges in flight;
    // edge pairs summed in fp16 (HADD2), pair-sums accumulated in fp32.
    {
        int g = lane >> 3;                // node group 0..3
        int c = lane & 7;                 // uint4 chunk (8 halfs)
        int nl = w * 4 + g;               // local node 0..63
        int n = row0 + nl;

        float2 A0[4], A1[4];
#pragma unroll
        for (int j = 0; j < 4; j++) {
            A0[j] = make_float2(0.f, 0.f);
            A1[j] = make_float2(0.f, 0.f);
        }
        int deg = 0;
        if (n < N_NODES) {
            int b = __ldg(&g_rowptr[n]);
            int e = __ldg(&g_rowptr[n + 1]);
            deg = e - b;
            int i = b;
            for (; i + 3 < e; i += 4) {
                int s0 = __ldg(&g_esrc[i]);
                int s1 = __ldg(&g_esrc[i + 1]);
                int s2 = __ldg(&g_esrc[i + 2]);
                int s3 = __ldg(&g_esrc[i + 3]);
                uint4 v0 = __ldg(&H[s0 * 8 + c]);
                uint4 v1 = __ldg(&H[s1 * 8 + c]);
                uint4 v2 = __ldg(&H[s2 * 8 + c]);
                uint4 v3 = __ldg(&H[s3 * 8 + c]);
                const __half2* p0 = (const __half2*)&v0;
                const __half2* p1 = (const __half2*)&v1;
                const __half2* p2 = (const __half2*)&v2;
                const __half2* p3 = (const __half2*)&v3;
#pragma unroll
                for (int j = 0; j < 4; j++) {
                    float2 f01 = __half22float2(__hadd2(p0[j], p1[j]));
                    float2 f23 = __half22float2(__hadd2(p2[j], p3[j]));
                    A0[j].x += f01.x; A0[j].y += f01.y;
                    A1[j].x += f23.x; A1[j].y += f23.y;
                }
            }
            if (i + 1 < e) {                 // 2-edge remainder
                int s0 = __ldg(&g_esrc[i]);
                int s1 = __ldg(&g_esrc[i + 1]);
                uint4 v0 = __ldg(&H[s0 * 8 + c]);
                uint4 v1 = __ldg(&H[s1 * 8 + c]);
                const __half2* p0 = (const __half2*)&v0;
                const __half2* p1 = (const __half2*)&v1;
#pragma unroll
                for (int j = 0; j < 4; j++) {
                    float2 f01 = __half22float2(__hadd2(p0[j], p1[j]));
                    A0[j].x += f01.x; A0[j].y += f01.y;
                }
                i += 2;
            }
            if (i < e) {                     // 1-edge remainder
                int s0 = __ldg(&g_esrc[i]);
                uint4 v0 = __ldg(&H[s0 * 8 + c]);
                const __half2* p0 = (const __half2*)&v0;
#pragma unroll
                for (int j = 0; j < 4; j++) {
                    float2 f0 = __half22float2(p0[j]);
                    A1[j].x += f0.x; A1[j].y += f0.y;
                }
            }
        }
        float inv = 1.0f / (float)(deg > 0 ? deg : 1);
        uint4 pack;
        pack.x = h2u(__floats2half2_rn((A0[0].x + A1[0].x) * inv,
                                       (A0[0].y + A1[0].y) * inv));
        pack.y = h2u(__floats2half2_rn((A0[1].x + A1[1].x) * inv,
                                       (A0[1].y + A1[1].y) * inv));
        pack.z = h2u(__floats2half2_rn((A0[2].x + A1[2].x) * inv,
                                       (A0[2].y + A1[2].y) * inv));
        pack.w = h2u(__floats2half2_rn((A0[3].x + A1[3].x) * inv,
                                       (A0[3].y + A1[3].y) * inv));
        *(uint4*)(sNh + nl * PITCH + c * 8) = pack;
    }

    __syncthreads();   // the only CTA-wide sync

    // ---- HMMA MAC: both phases accumulate into the same C fragments ----
    const int wm = w & 3, wn = w >> 2;

    const int aRow  = wm * 16 + (lane & 7) + ((lane >> 3) & 1) * 8;
    const int aColH = (lane >> 4) * 8;
    const int bl    = lane & 15;
    const int bRow  = wn * 16 + (bl & 7);       // W row = output col n
    const int bColH = ((bl >> 3) & 1) * 8;      // tile1 = k-offset +8

    float C0[4] = {0.f, 0.f, 0.f, 0.f};
    float C1[4] = {0.f, 0.f, 0.f, 0.f};

#pragma unroll
    for (int ph = 0; ph < 2; ph++) {
        const __half* Xs = ph ? sNh : sXh;
        const __half* Ws = ph ? sWnh : sWsh;
#pragma unroll
        for (int kk = 0; kk < 4; kk++) {
            int k0 = kk * 16;
            uint32_t a0, a1, a2, a3;
            uint32_t aaddr = s2u(Xs + aRow * PITCH + k0 + aColH);
            asm volatile(
                "ldmatrix.sync.aligned.m8n8.x4.shared.b16 {%0,%1,%2,%3}, [%4];"
                : "=r"(a0), "=r"(a1), "=r"(a2), "=r"(a3) : "r"(aaddr));

            uint32_t b0, b1, b2, b3;
            uint32_t baddr0 = s2u(Ws + bRow * PITCH + k0 + bColH);
            uint32_t baddr1 = s2u(Ws + (bRow + 8) * PITCH + k0 + bColH);
            asm volatile(
                "ldmatrix.sync.aligned.m8n8.x2.shared.b16 {%0,%1}, [%2];"
                : "=r"(b0), "=r"(b1) : "r"(baddr0));
            asm volatile(
                "ldmatrix.sync.aligned.m8n8.x2.shared.b16 {%0,%1}, [%2];"
                : "=r"(b2), "=r"(b3) : "r"(baddr1));

            asm volatile(
                "mma.sync.aligned.m16n8k16.row.col.f32.f16.f16.f32 "
                "{%0,%1,%2,%3}, {%4,%5,%6,%7}, {%8,%9}, {%0,%1,%2,%3};"
                : "+f"(C0[0]), "+f"(C0[1]), "+f"(C0[2]), "+f"(C0[3])
                : "r"(a0), "r"(a1), "r"(a2), "r"(a3), "r"(b0), "r"(b1));
            asm volatile(
                "mma.sync.aligned.m16n8k16.row.col.f32.f16.f16.f32 "
                "{%0,%1,%2,%3}, {%4,%5,%6,%7}, {%8,%9}, {%0,%1,%2,%3};"
                : "+f"(C1[0]), "+f"(C1[1]), "+f"(C1[2]), "+f"(C1[3])
                : "r"(a0), "r"(a1), "r"(a2), "r"(a3), "r"(b2), "r"(b3));
        }
    }

    // ---- Epilogue: bias (+relu). Layer 1 -> fp16 g_h1h; layer 2 -> fp32 out ----
    {
        int g  = lane >> 2;
        int tg = lane & 3;
        int c  = wn * 16 + tg * 2;           // C0 cols c,c+1; C1 cols c+8,c+9
        int gr0 = row0 + wm * 16 + g;
        int gr1 = gr0 + 8;

        float bv0 = __ldg(&bias[c]);
        float bv1 = __ldg(&bias[c + 1]);
        float bv8 = __ldg(&bias[c + 8]);
        float bv9 = __ldg(&bias[c + 9]);

        float o00 = C0[0] + bv0, o01 = C0[1] + bv1;   // row gr0
        float o10 = C0[2] + bv0, o11 = C0[3] + bv1;   // row gr1
        float o08 = C1[0] + bv8, o09 = C1[1] + bv9;   // row gr0 (+8 cols)
        float o18 = C1[2] + bv8, o19 = C1[3] + bv9;   // row gr1

        if (LAYER1) {
            o00 = fmaxf(o00, 0.f); o01 = fmaxf(o01, 0.f);
            o10 = fmaxf(o10, 0.f); o11 = fmaxf(o11, 0.f);
            o08 = fmaxf(o08, 0.f); o09 = fmaxf(o09, 0.f);
            o18 = fmaxf(o18, 0.f); o19 = fmaxf(o19, 0.f);
            __half2* hp = (__half2*)g_h1h;
            if (gr0 < N_NODES) {
                hp[(gr0 * 64 + c) >> 1]     = __floats2half2_rn(o00, o01);
                hp[(gr0 * 64 + c + 8) >> 1] = __floats2half2_rn(o08, o09);
            }
            if (gr1 < N_NODES) {
                hp[(gr1 * 64 + c) >> 1]     = __floats2half2_rn(o10, o11);
                hp[(gr1 * 64 + c + 8) >> 1] = __floats2half2_rn(o18, o19);
            }
        } else {
            if (gr0 < N_NODES) {
                *(float2*)(outp + gr0 * 64 + c)     = make_float2(o00, o01);
                *(float2*)(outp + gr0 * 64 + c + 8) = make_float2(o08, o09);
            }
            if (gr1 < N_NODES) {
                *(float2*)(outp + gr1 * 64 + c)     = make_float2(o10, o11);
                *(float2*)(outp + gr1 * 64 + c + 8) = make_float2(o18, o19);
            }
        }
    }
}

// ---------------- Launch ----------------
extern "C" void kernel_launch(void* const* d_in, const int* in_sizes, int n_in,
                              void* d_out, int out_size) {
    const float* in_feat = (const float*)d_in[0];
    const int*   src     = (const int*)d_in[1];
    const int*   dst     = (const int*)d_in[2];
    const float* Ws1     = (const float*)d_in[3];
    const float* Wn1     = (const float*)d_in[4];
    const float* b1      = (const float*)d_in[5];
    const float* Ws2     = (const float*)d_in[6];
    const float* Wn2     = (const float*)d_in[7];
    const float* b2      = (const float*)d_in[8];
    float*       out     = (float*)d_out;

    const int e_blocks    = (N_EDGES + 255) / 256;   // 6250
    const int fuse_blocks = (N_NODES + 63) / 64;     // 1563

    csr_hist_cast<<<e_blocks, 256>>>(dst, (const float4*)in_feat);   // 0
    scan_lookback<<<NB_SCAN, 512>>>();                               // 1
    csr_scatter<<<e_blocks, 256>>>(src, dst);                        // 2
    sage_fused<true><<<fuse_blocks, 512>>>(Ws1, Wn1, b1, nullptr);   // 3 (profiled)
    sage_fused<false><<<fuse_blocks, 512>>>(Ws2, Wn2, b2, out);      // 4
}

// round 15
// speedup vs baseline: 1.1276x; 1.1276x over previous
#include <cuda_runtime.h>
#include <cuda_fp16.h>
#include <cstdint>

#define N_NODES 100000
#define N_EDGES 1600000
#define NB_SCAN 196            // ceil(100000/512)

// Persistent scratch (zero-initialized at module load; scatter re-zeros
// g_degi/g_bsum each call so every graph replay sees the same state).
__device__ __half g_xh [N_NODES * 64];   // fp16 mirror of in_feat
__device__ __half g_h1h[N_NODES * 64];   // fp16 layer-1 output
__device__ int    g_degi[N_NODES];
__device__ int    g_rowptr[N_NODES + 1];
__device__ int    g_cursor[N_NODES];
__device__ int    g_esrc[N_EDGES];
__device__ int    g_bsum[NB_SCAN];

// ---------------- helpers ----------------
__device__ __forceinline__ void st_release(int* p, int v) {
    asm volatile("st.release.gpu.b32 [%0], %1;" :: "l"(p), "r"(v) : "memory");
}
__device__ __forceinline__ int ld_acquire(const int* p) {
    int v;
    asm volatile("ld.acquire.gpu.b32 %0, [%1];" : "=r"(v) : "l"(p) : "memory");
    return v;
}
__device__ __forceinline__ uint32_t s2u(const void* p) {
    return (uint32_t)__cvta_generic_to_shared(p);
}
__device__ __forceinline__ uint32_t h2u(__half2 h) {
    uint32_t u;
    memcpy(&u, &h, 4);
    return u;
}

// ---------------- CSR build ----------------
// (0) histogram + fp16 cast of in_feat.
__global__ void csr_hist_cast(const int* __restrict__ dst,
                              const float4* __restrict__ xin) {
    int e = blockIdx.x * blockDim.x + threadIdx.x;
    if (e < N_EDGES) {
        atomicAdd(&g_degi[dst[e]], 1);
        float4 v = __ldg(&xin[e]);
        __half2* xh2 = (__half2*)g_xh;
        xh2[2 * e]     = __floats2half2_rn(v.x, v.y);
        xh2[2 * e + 1] = __floats2half2_rn(v.z, v.w);
    }
}

// (1) single-pass scan with lookback.
__global__ void scan_lookback() {
    __shared__ int sh[512];
    int t = threadIdx.x, bid = blockIdx.x;
    int idx = bid * 512 + t;
    int v = (idx < N_NODES) ? g_degi[idx] : 0;

    sh[t] = v;
    __syncthreads();
    for (int off = 1; off < 512; off <<= 1) {
        int x = (t >= off) ? sh[t - off] : 0;
        __syncthreads();
        sh[t] += x;
        __syncthreads();
    }
    int incl = sh[t];
    int btot = sh[511];
    if (t == 0) st_release(&g_bsum[bid], btot + 1);

    int pre = 0;
    if (t < bid) {
        int x;
        do { x = ld_acquire(&g_bsum[t]); } while (x == 0);
        pre = x - 1;
    }
    __syncthreads();
    sh[t] = pre;
    __syncthreads();
    for (int off = 256; off > 0; off >>= 1) {
        if (t < off) sh[t] += sh[t + off];
        __syncthreads();
    }
    int excl = incl - v + sh[0];
    if (idx < N_NODES) {
        g_rowptr[idx] = excl;
        g_cursor[idx] = excl;
    }
    if (bid == 0 && t == 0) g_rowptr[N_NODES] = N_EDGES;
}

// (2) scatter + reset degi/bsum for next replay.
__global__ void csr_scatter(const int* __restrict__ src,
                            const int* __restrict__ dst) {
    int e = blockIdx.x * blockDim.x + threadIdx.x;
    if (e < N_EDGES) {
        int p = atomicAdd(&g_cursor[dst[e]], 1);
        g_esrc[p] = src[e];
    }
    if (e < N_NODES) g_degi[e] = 0;
    if (e < NB_SCAN) g_bsum[e] = 0;
}

// ---------------- Fused layer: fp16 gather-mean + HMMA dual GEMM ----------------
// out = act( X @ Ws^T + mean_neigh(X) @ Wn^T + b ), X fp16, fp32 accumulate.
// R13 gather (2-edge unroll, fp32 accumulate) + rowptr loads hoisted to top.
#define PITCH 72

template <bool LAYER1>
__global__ void __launch_bounds__(512)
sage_fused(const float* __restrict__ Wself,
           const float* __restrict__ Wneigh,
           const float* __restrict__ bias,
           float* __restrict__ outp) {
    __shared__ __align__(16) __half sXh[64 * PITCH];
    __shared__ __align__(16) __half sNh[64 * PITCH];
    __shared__ __align__(16) __half sWsh[64 * PITCH];
    __shared__ __align__(16) __half sWnh[64 * PITCH];

    const uint4* H = LAYER1 ? (const uint4*)g_xh : (const uint4*)g_h1h;

    const int tid  = threadIdx.x;
    const int w    = tid >> 5;
    const int lane = tid & 31;
    const int row0 = blockIdx.x * 64;

    // ---- Hoisted gather row-range loads (start the dependent chain NOW) ----
    const int gnl = w * 4 + (lane >> 3);       // this thread's gather node 0..63
    const int gn  = row0 + gnl;
    int gb = 0, ge = 0;
    if (gn < N_NODES) {
        gb = __ldg(&g_rowptr[gn]);
        ge = __ldg(&g_rowptr[gn + 1]);
    }

    // ---- Stage self tile (fp16 rows straight from H) ----
    {
        int r = tid >> 3, c = tid & 7;       // 64 rows x 8 uint4 chunks
        int gr = row0 + r;
        uint4 v = make_uint4(0u, 0u, 0u, 0u);
        if (gr < N_NODES) v = __ldg(&H[gr * 8 + c]);
        *(uint4*)(sXh + r * PITCH + c * 8) = v;
    }

    // ---- Stage weights fp32 -> fp16 ([n][k] layout) ----
    {
        const float4* Ws4 = (const float4*)Wself;
        const float4* Wn4 = (const float4*)Wneigh;
#pragma unroll
        for (int l = 0; l < 2; l++) {
            int i = tid + l * 512;           // 0..1023 float4 index
            int r = i >> 4, f = i & 15;      // row (n), 4-col (k) chunk
            float4 a = __ldg(&Ws4[i]);
            float4 b = __ldg(&Wn4[i]);
            __half2* ps = (__half2*)(sWsh + r * PITCH + f * 4);
            __half2* pn = (__half2*)(sWnh + r * PITCH + f * 4);
            ps[0] = __floats2half2_rn(a.x, a.y);
            ps[1] = __floats2half2_rn(a.z, a.w);
            pn[0] = __floats2half2_rn(b.x, b.y);
            pn[1] = __floats2half2_rn(b.z, b.w);
        }
    }

    // ---- Gather-mean (fp16 rows, 128B = 1 line/edge) -> sNh ----
    // 8 lanes per node -> 4 nodes concurrently per warp; 2 edges in flight.
    {
        int c = lane & 7;                 // uint4 chunk (8 halfs)

        float2 a0[4], a1[4];
#pragma unroll
        for (int j = 0; j < 4; j++) {
            a0[j] = make_float2(0.f, 0.f);
            a1[j] = make_float2(0.f, 0.f);
        }
        int i = gb;
        for (; i + 1 < ge; i += 2) {
            int s0 = __ldg(&g_esrc[i]);
            int s1 = __ldg(&g_esrc[i + 1]);
            uint4 v0 = __ldg(&H[s0 * 8 + c]);
            uint4 v1 = __ldg(&H[s1 * 8 + c]);
            const __half2* p0 = (const __half2*)&v0;
            const __half2* p1 = (const __half2*)&v1;
#pragma unroll
            for (int j = 0; j < 4; j++) {
                float2 f0 = __half22float2(p0[j]);
                float2 f1 = __half22float2(p1[j]);
                a0[j].x += f0.x; a0[j].y += f0.y;
                a1[j].x += f1.x; a1[j].y += f1.y;
            }
        }
        if (i < ge) {
            int s0 = __ldg(&g_esrc[i]);
            uint4 v0 = __ldg(&H[s0 * 8 + c]);
            const __half2* p0 = (const __half2*)&v0;
#pragma unroll
            for (int j = 0; j < 4; j++) {
                float2 f0 = __half22float2(p0[j]);
                a0[j].x += f0.x; a0[j].y += f0.y;
            }
        }
        int deg = ge - gb;
        float inv = 1.0f / (float)(deg > 0 ? deg : 1);
        uint4 pack;
        pack.x = h2u(__floats2half2_rn((a0[0].x + a1[0].x) * inv,
                                       (a0[0].y + a1[0].y) * inv));
        pack.y = h2u(__floats2half2_rn((a0[1].x + a1[1].x) * inv,
                                       (a0[1].y + a1[1].y) * inv));
        pack.z = h2u(__floats2half2_rn((a0[2].x + a1[2].x) * inv,
                                       (a0[2].y + a1[2].y) * inv));
        pack.w = h2u(__floats2half2_rn((a0[3].x + a1[3].x) * inv,
                                       (a0[3].y + a1[3].y) * inv));
        *(uint4*)(sNh + gnl * PITCH + c * 8) = pack;
    }

    __syncthreads();   // the only CTA-wide sync

    // ---- HMMA MAC: both phases accumulate into the same C fragments ----
    const int wm = w & 3, wn = w >> 2;

    const int aRow  = wm * 16 + (lane & 7) + ((lane >> 3) & 1) * 8;
    const int aColH = (lane >> 4) * 8;
    const int bl    = lane & 15;
    const int bRow  = wn * 16 + (bl & 7);       // W row = output col n
    const int bColH = ((bl >> 3) & 1) * 8;      // tile1 = k-offset +8

    float C0[4] = {0.f, 0.f, 0.f, 0.f};
    float C1[4] = {0.f, 0.f, 0.f, 0.f};

#pragma unroll
    for (int ph = 0; ph < 2; ph++) {
        const __half* Xs = ph ? sNh : sXh;
        const __half* Ws = ph ? sWnh : sWsh;
#pragma unroll
        for (int kk = 0; kk < 4; kk++) {
            int k0 = kk * 16;
            uint32_t a0, a1, a2, a3;
            uint32_t aaddr = s2u(Xs + aRow * PITCH + k0 + aColH);
            asm volatile(
                "ldmatrix.sync.aligned.m8n8.x4.shared.b16 {%0,%1,%2,%3}, [%4];"
                : "=r"(a0), "=r"(a1), "=r"(a2), "=r"(a3) : "r"(aaddr));

            uint32_t b0, b1, b2, b3;
            uint32_t baddr0 = s2u(Ws + bRow * PITCH + k0 + bColH);
            uint32_t baddr1 = s2u(Ws + (bRow + 8) * PITCH + k0 + bColH);
            asm volatile(
                "ldmatrix.sync.aligned.m8n8.x2.shared.b16 {%0,%1}, [%2];"
                : "=r"(b0), "=r"(b1) : "r"(baddr0));
            asm volatile(
                "ldmatrix.sync.aligned.m8n8.x2.shared.b16 {%0,%1}, [%2];"
                : "=r"(b2), "=r"(b3) : "r"(baddr1));

            asm volatile(
                "mma.sync.aligned.m16n8k16.row.col.f32.f16.f16.f32 "
                "{%0,%1,%2,%3}, {%4,%5,%6,%7}, {%8,%9}, {%0,%1,%2,%3};"
                : "+f"(C0[0]), "+f"(C0[1]), "+f"(C0[2]), "+f"(C0[3])
                : "r"(a0), "r"(a1), "r"(a2), "r"(a3), "r"(b0), "r"(b1));
            asm volatile(
                "mma.sync.aligned.m16n8k16.row.col.f32.f16.f16.f32 "
                "{%0,%1,%2,%3}, {%4,%5,%6,%7}, {%8,%9}, {%0,%1,%2,%3};"
                : "+f"(C1[0]), "+f"(C1[1]), "+f"(C1[2]), "+f"(C1[3])
                : "r"(a0), "r"(a1), "r"(a2), "r"(a3), "r"(b2), "r"(b3));
        }
    }

    // ---- Epilogue: bias (+relu). Layer 1 -> fp16 g_h1h; layer 2 -> fp32 out ----
    {
        int g  = lane >> 2;
        int tg = lane & 3;
        int c  = wn * 16 + tg * 2;           // C0 cols c,c+1; C1 cols c+8,c+9
        int gr0 = row0 + wm * 16 + g;
        int gr1 = gr0 + 8;

        float bv0 = __ldg(&bias[c]);
        float bv1 = __ldg(&bias[c + 1]);
        float bv8 = __ldg(&bias[c + 8]);
        float bv9 = __ldg(&bias[c + 9]);

        float o00 = C0[0] + bv0, o01 = C0[1] + bv1;   // row gr0
        float o10 = C0[2] + bv0, o11 = C0[3] + bv1;   // row gr1
        float o08 = C1[0] + bv8, o09 = C1[1] + bv9;   // row gr0 (+8 cols)
        float o18 = C1[2] + bv8, o19 = C1[3] + bv9;   // row gr1

        if (LAYER1) {
            o00 = fmaxf(o00, 0.f); o01 = fmaxf(o01, 0.f);
            o10 = fmaxf(o10, 0.f); o11 = fmaxf(o11, 0.f);
            o08 = fmaxf(o08, 0.f); o09 = fmaxf(o09, 0.f);
            o18 = fmaxf(o18, 0.f); o19 = fmaxf(o19, 0.f);
            __half2* hp = (__half2*)g_h1h;
            if (gr0 < N_NODES) {
                hp[(gr0 * 64 + c) >> 1]     = __floats2half2_rn(o00, o01);
                hp[(gr0 * 64 + c + 8) >> 1] = __floats2half2_rn(o08, o09);
            }
            if (gr1 < N_NODES) {
                hp[(gr1 * 64 + c) >> 1]     = __floats2half2_rn(o10, o11);
                hp[(gr1 * 64 + c + 8) >> 1] = __floats2half2_rn(o18, o19);
            }
        } else {
            if (gr0 < N_NODES) {
                *(float2*)(outp + gr0 * 64 + c)     = make_float2(o00, o01);
                *(float2*)(outp + gr0 * 64 + c + 8) = make_float2(o08, o09);
            }
            if (gr1 < N_NODES) {
                *(float2*)(outp + gr1 * 64 + c)     = make_float2(o10, o11);
                *(float2*)(outp + gr1 * 64 + c + 8) = make_float2(o18, o19);
            }
        }
    }
}

// ---------------- Launch ----------------
extern "C" void kernel_launch(void* const* d_in, const int* in_sizes, int n_in,
                              void* d_out, int out_size) {
    const float* in_feat = (const float*)d_in[0];
    const int*   src     = (const int*)d_in[1];
    const int*   dst     = (const int*)d_in[2];
    const float* Ws1     = (const float*)d_in[3];
    const float* Wn1     = (const float*)d_in[4];
    const float* b1      = (const float*)d_in[5];
    const float* Ws2     = (const float*)d_in[6];
    const float* Wn2     = (const float*)d_in[7];
    const float* b2      = (const float*)d_in[8];
    float*       out     = (float*)d_out;

    const int e_blocks    = (N_EDGES + 255) / 256;   // 6250
    const int fuse_blocks = (N_NODES + 63) / 64;     // 1563

    csr_hist_cast<<<e_blocks, 256>>>(dst, (const float4*)in_feat);   // 0
    scan_lookback<<<NB_SCAN, 512>>>();                               // 1
    csr_scatter<<<e_blocks, 256>>>(src, dst);                        // 2
    sage_fused<true><<<fuse_blocks, 512>>>(Ws1, Wn1, b1, nullptr);   // 3 (profiled)
    sage_fused<false><<<fuse_blocks, 512>>>(Ws2, Wn2, b2, out);      // 4
}